// round 7
// baseline (speedup 1.0000x reference)
#include <cuda_runtime.h>
#include <cstdint>

#define NBB 4
#define QLEN 4
#define HIDDEN 4096
#define NHEADS 32
#define NKVH 8
#define HDIM 128
#define PRIORLEN 4096
#define BQ 16
#define NCHUNK 16          /* chunks per (b,kvh) pair */
#define CHUNK 256          /* keys per chunk */
#define QK_SCALE 0.08838834764831845f   /* 1/sqrt(128) */
#define LOG2E 1.4426950408889634f

#define KST_STRIDE 132     /* floats; 132 mod 32 = 4 -> conflict-free LDS/STS.128 */
#define P2_STRIDE  18      /* float2; 36 words mod 32 = 4 -> conflict-free STS.128 */

typedef unsigned long long ull;

union F4U { float4 f; ull u[2]; };

__device__ __forceinline__ void fma2(ull &d, ull a, ull b) {
    asm("fma.rn.f32x2 %0, %1, %2, %0;" : "+l"(d) : "l"(a), "l"(b));
}
__device__ __forceinline__ float lo32(ull v) { return __uint_as_float((unsigned)(v & 0xffffffffull)); }
__device__ __forceinline__ float hi32(ull v) { return __uint_as_float((unsigned)(v >> 32)); }
__device__ __forceinline__ ull dup2(float x) {
    ull r; asm("mov.b64 %0, {%1, %1};" : "=l"(r) : "f"(x)); return r;
}

// ---------------- scratch (static device globals; no runtime alloc) ----------------
__device__ __align__(16) float g_part_qkv[32][BQ][6144];      // 12.6 MB
__device__ __align__(16) float g_q[NBB][NHEADS][QLEN][HDIM];  // scaled + rope'd
__device__ __align__(16) float g_kact[NBB][NKVH][QLEN][HDIM];
__device__ __align__(16) float g_vact[NBB][NKVH][QLEN][HDIM];
__device__ __align__(16) float g_m[32][NCHUNK][16];
__device__ __align__(16) float g_l[32][NCHUNK][16];
__device__ __align__(16) float g_o[32][NCHUNK][16][HDIM];     // 4.2 MB
__device__ __align__(16) float g_attn[BQ][4096];

// ---------------- kernel 1: QKV projection partials (k-split GEMM) ----------------
__global__ void __launch_bounds__(128) k_proj(const float* __restrict__ h,
                                              const float* __restrict__ wq,
                                              const float* __restrict__ wk,
                                              const float* __restrict__ wv)
{
    __shared__ float2 hs[16][128];
    const int tile = blockIdx.x;     // 0..11
    const int ks   = blockIdx.y;     // 0..31
    const int tid  = threadIdx.x;

    for (int i = tid; i < 16 * 128; i += 128) {
        int r = i >> 7, c = i & 127;
        float v = h[r * HIDDEN + ks * 128 + c];
        hs[r][c] = make_float2(v, v);
    }
    __syncthreads();

    const float* wbase; int wstride, colbase;
    if (tile < 8)       { wbase = wq; wstride = 4096; colbase = tile * 512; }
    else if (tile < 10) { wbase = wk; wstride = 1024; colbase = (tile - 8) * 512; }
    else                { wbase = wv; wstride = 1024; colbase = (tile - 10) * 512; }

    const float* wp = wbase + (size_t)(ks * 128) * wstride + colbase + tid * 4;

    ull accA[16], accB[16];
#pragma unroll
    for (int r = 0; r < 16; r++) { accA[r] = 0ull; accB[r] = 0ull; }

#pragma unroll 8
    for (int kk = 0; kk < 128; kk++) {
        F4U w; w.f = *reinterpret_cast<const float4*>(wp);
        wp += wstride;
#pragma unroll
        for (int r = 0; r < 16; r++) {
            ull h2 = *reinterpret_cast<const ull*>(&hs[r][kk]);
            fma2(accA[r], h2, w.u[0]);
            fma2(accB[r], h2, w.u[1]);
        }
    }

    const int gcol = tile * 512 + tid * 4;
#pragma unroll
    for (int r = 0; r < 16; r++) {
        F4U o; o.u[0] = accA[r]; o.u[1] = accB[r];
        *reinterpret_cast<float4*>(&g_part_qkv[ks][r][gcol]) = o.f;
    }
}

// ---------------- kernel 2: reduce partials + RoPE (+ zero d_out for k_oproj REDs)
__global__ void __launch_bounds__(128) k_rope(float* __restrict__ out)
{
    __shared__ float sv[128];
    const int colblk = blockIdx.x;   // 0..47
    const int row    = blockIdx.y;   // 0..15
    const int tid    = threadIdx.x;
    const int col    = colblk * 128 + tid;

    // zero d_out (65536 floats) using the first 512 of 768 blocks
    const int zb = row * 48 + colblk;
    if (zb < 512) out[zb * 128 + tid] = 0.f;

    float v = 0.f;
#pragma unroll
    for (int s = 0; s < 32; s++) v += g_part_qkv[s][row][col];

    const int b = row >> 2, ql = row & 3;

    if (colblk < 40) {
        sv[tid] = v;
        __syncthreads();
        const int d = tid;
        const int j = d & 63;
        float rot = (d < 64) ? -sv[d + 64] : sv[d - 64];
        float invf = (float)exp(-(double)j * (13.815510557964274 / 64.0)); // log(1e6)/64
        float pos  = (float)(PRIORLEN + ql);
        float ang  = pos * invf;
        double ad  = (double)ang;
        float c = (float)cos(ad);
        float s = (float)sin(ad);
        float outv = v * c + rot * s;
        if (colblk < 32) {
            g_q[b][colblk][ql][d] = outv * QK_SCALE;
        } else {
            g_kact[b][colblk - 32][ql][d] = outv;
        }
    } else {
        g_vact[b][colblk - 40][ql][tid] = v;
    }
}

// ---------------- kernel 3: split-KV attention partials (v3: smem-staged K) -------
// grid (NCHUNK, 32 pairs), 128 threads. Chunk = 256 keys staged in two 128-key
// halves through smem (coalesced LDG, conflict-free LDS.128). Thread owns keys
// {tid, tid+128}; dots accumulate fully in-register (no per-key shuffles).
// Dynamic smem layout:
//   float  kst [128*132]                67,584 B
//   float2 q2s [128][8]                  8,192 B
//   float2 p2  [256][18] (16 qi used)   36,864 B
//   float  wm[4][16], wl[4][16]            512 B     total 113,152 B
#define SMEM_ATTN 113152

__global__ void __launch_bounds__(128) k_attn(const float* __restrict__ pk,
                                              const float* __restrict__ pv)
{
    extern __shared__ char smraw[];
    float*  kst = reinterpret_cast<float*>(smraw);
    float2* q2s = reinterpret_cast<float2*>(smraw + 67584);          // [d][qp]
    float2* p2  = reinterpret_cast<float2*>(smraw + 67584 + 8192);   // [key][qi]
    float*  wm  = reinterpret_cast<float*>(smraw + 67584 + 8192 + 36864);
    float*  wl  = wm + 64;

    const int pair = blockIdx.y;       // 0..31
    const int cblk = blockIdx.x;       // 0..NCHUNK-1
    const int b = pair >> 3, kvh = pair & 7;
    const int tid = threadIdx.x;
    const int w = tid >> 5, lane = tid & 31;
    const int key0 = cblk * CHUNK;

    // stage q into smem as f32x2 qi-pairs (qi = hl*4+ql), d = tid
    {
        const int d = tid;
#pragma unroll
        for (int qp = 0; qp < 8; qp++) {
            int qi0 = 2 * qp, qi1 = 2 * qp + 1;
            float a = g_q[b][kvh * 4 + (qi0 >> 2)][qi0 & 3][d];
            float c = g_q[b][kvh * 4 + (qi1 >> 2)][qi1 & 3][d];
            q2s[d * 8 + qp] = make_float2(a, c);
        }
    }

    const float* kchunk = pk + ((size_t)(b * NKVH + kvh) * PRIORLEN + key0) * HDIM;

    ull acc0[8], acc1[8];
#pragma unroll
    for (int qp = 0; qp < 8; qp++) { acc0[qp] = 0ull; acc1[qp] = 0ull; }

#pragma unroll
    for (int half = 0; half < 2; half++) {
        __syncthreads();   // q2s ready (half 0) / prior half's reads done (half 1)
        // ---- stage 128 keys coalesced: warp w stages keys [w*32, w*32+32) ----
        const float* kb = kchunk + (size_t)(half * 128) * HDIM;
#pragma unroll 8
        for (int kk = 0; kk < 32; kk++) {
            int key = w * 32 + kk;
            float4 kv = *reinterpret_cast<const float4*>(kb + (size_t)key * HDIM + lane * 4);
            *reinterpret_cast<float4*>(&kst[key * KST_STRIDE + lane * 4]) = kv;
        }
        __syncthreads();

        // ---- score: thread-per-key register dot products over staged K ----
        ull* acc = half ? acc1 : acc0;
#pragma unroll 4
        for (int d4 = 0; d4 < 128; d4 += 4) {
            float4 kv = *reinterpret_cast<const float4*>(&kst[tid * KST_STRIDE + d4]);
            float ka[4] = {kv.x, kv.y, kv.z, kv.w};
#pragma unroll
            for (int dd = 0; dd < 4; dd++) {
                ull kd = dup2(ka[dd]);
                const float4* qrow = reinterpret_cast<const float4*>(&q2s[(d4 + dd) * 8]);
#pragma unroll
                for (int q4 = 0; q4 < 4; q4++) {
                    F4U qq; qq.f = qrow[q4];   // broadcast LDS.128: 2 qp pairs
                    fma2(acc[q4 * 2],     kd, qq.u[0]);
                    fma2(acc[q4 * 2 + 1], kd, qq.u[1]);
                }
            }
        }
    }

    // unpack scores: s0/s1[qi] for keys tid, tid+128
    float s0[16], s1[16];
#pragma unroll
    for (int qp = 0; qp < 8; qp++) {
        s0[2 * qp] = lo32(acc0[qp]); s0[2 * qp + 1] = hi32(acc0[qp]);
        s1[2 * qp] = lo32(acc1[qp]); s1[2 * qp + 1] = hi32(acc1[qp]);
    }

    // ---- chunk max per qi ----
    float m16[16];
#pragma unroll
    for (int qi = 0; qi < 16; qi++) m16[qi] = fmaxf(s0[qi], s1[qi]);
#pragma unroll
    for (int off = 16; off >= 1; off >>= 1) {
#pragma unroll
        for (int qi = 0; qi < 16; qi++)
            m16[qi] = fmaxf(m16[qi], __shfl_xor_sync(0xffffffffu, m16[qi], off));
    }
    if (lane == 0) {
#pragma unroll
        for (int qi = 0; qi < 16; qi++) wm[w * 16 + qi] = m16[qi];
    }
    __syncthreads();

    // ---- exp + l ; probs stored key-major duplicated ----
    float p0[16], p1[16], l16[16];
#pragma unroll
    for (int qi = 0; qi < 16; qi++) {
        float mq = fmaxf(fmaxf(wm[qi], wm[16 + qi]), fmaxf(wm[32 + qi], wm[48 + qi]));
        p0[qi] = exp2f((s0[qi] - mq) * LOG2E);
        p1[qi] = exp2f((s1[qi] - mq) * LOG2E);
        l16[qi] = p0[qi] + p1[qi];
    }
#pragma unroll
    for (int qp = 0; qp < 8; qp++) {
        *reinterpret_cast<float4*>(&p2[tid * P2_STRIDE + 2 * qp]) =
            make_float4(p0[2 * qp], p0[2 * qp], p0[2 * qp + 1], p0[2 * qp + 1]);
        *reinterpret_cast<float4*>(&p2[(tid + 128) * P2_STRIDE + 2 * qp]) =
            make_float4(p1[2 * qp], p1[2 * qp], p1[2 * qp + 1], p1[2 * qp + 1]);
    }
#pragma unroll
    for (int off = 16; off >= 1; off >>= 1) {
#pragma unroll
        for (int qi = 0; qi < 16; qi++)
            l16[qi] += __shfl_xor_sync(0xffffffffu, l16[qi], off);
    }
    if (lane == 0) {
#pragma unroll
        for (int qi = 0; qi < 16; qi++) wl[w * 16 + qi] = l16[qi];
    }
    __syncthreads();
    if (tid < 16) {
        g_m[pair][cblk][tid] = fmaxf(fmaxf(wm[tid], wm[16 + tid]), fmaxf(wm[32 + tid], wm[48 + tid]));
        g_l[pair][cblk][tid] = wl[tid] + wl[16 + tid] + wl[32 + tid] + wl[48 + tid];
    }

    // ---- PV phase: warp w handles keys [w*64, w*64+64), lane = dim-group ----
    ull oA[16], oB[16];
#pragma unroll
    for (int qi = 0; qi < 16; qi++) { oA[qi] = 0ull; oB[qi] = 0ull; }
    const float* vb = pv + ((size_t)(b * NKVH + kvh) * PRIORLEN + key0 + w * 64) * HDIM + lane * 4;
#pragma unroll 4
    for (int i = 0; i < 64; i++) {
        F4U vt; vt.f = *reinterpret_cast<const float4*>(vb + (size_t)i * HDIM);
        const int key = w * 64 + i;
        const float4* prow = reinterpret_cast<const float4*>(&p2[key * P2_STRIDE]);
#pragma unroll
        for (int q4 = 0; q4 < 8; q4++) {
            F4U pp; pp.f = prow[q4];   // broadcast LDS.128: probs for qi pair
            fma2(oA[2 * q4],     pp.u[0], vt.u[0]);
            fma2(oB[2 * q4],     pp.u[0], vt.u[1]);
            fma2(oA[2 * q4 + 1], pp.u[1], vt.u[0]);
            fma2(oB[2 * q4 + 1], pp.u[1], vt.u[1]);
        }
    }
    __syncthreads();   // everyone done with p2/kst reads

    // reduce 4 warp partials through smem (overlay on kst: 32KB needed, 66KB avail)
    float* osum = kst;
#pragma unroll
    for (int qi = 0; qi < 16; qi++) {
        F4U o; o.u[0] = oA[qi]; o.u[1] = oB[qi];
        *reinterpret_cast<float4*>(&osum[(w * 16 + qi) * 128 + lane * 4]) = o.f;
    }
    __syncthreads();
#pragma unroll
    for (int i = 0; i < 16; i++) {
        int idx = i * 128 + tid;          // qi = i, d = tid
        float v = osum[idx] + osum[2048 + idx] + osum[4096 + idx] + osum[6144 + idx];
        g_o[pair][cblk][i][tid] = v;
    }
}

// ---------------- kernel 4: combine chunks + causal active keys ----------------
__global__ void __launch_bounds__(128) k_combine()
{
    __shared__ float wc_s[NCHUNK], wl_s[NCHUNK], sact[4];
    const int qi = blockIdx.x, pair = blockIdx.y;
    const int b = pair >> 3, kvh = pair & 7, hl = qi >> 2, ql = qi & 3;
    const int h = kvh * 4 + hl;
    const int tid = threadIdx.x, w = tid >> 5, lane = tid & 31;

    {
        float4 qv = *reinterpret_cast<const float4*>(&g_q[b][h][ql][lane * 4]);
        float4 kv = *reinterpret_cast<const float4*>(&g_kact[b][kvh][w][lane * 4]);
        float d = qv.x * kv.x + qv.y * kv.y + qv.z * kv.z + qv.w * kv.w;
#pragma unroll
        for (int off = 16; off >= 1; off >>= 1) d += __shfl_xor_sync(0xffffffffu, d, off);
        if (lane == 0) sact[w] = d;
    }
    if (tid < NCHUNK) wc_s[tid] = g_m[pair][tid][qi];
    __syncthreads();

    float M = -3.0e38f;
#pragma unroll
    for (int c = 0; c < NCHUNK; c++) M = fmaxf(M, wc_s[c]);
#pragma unroll
    for (int k2 = 0; k2 < 4; k2++) if (k2 <= ql) M = fmaxf(M, sact[k2]);
    __syncthreads();

    if (tid < NCHUNK) {
        float e = exp2f((wc_s[tid] - M) * LOG2E);
        wl_s[tid] = e * g_l[pair][tid][qi];
        wc_s[tid] = e;
    }
    __syncthreads();

    float L = 0.f;
#pragma unroll
    for (int c = 0; c < NCHUNK; c++) L += wl_s[c];
    float pact[4];
#pragma unroll
    for (int k2 = 0; k2 < 4; k2++) {
        pact[k2] = (k2 <= ql) ? exp2f((sact[k2] - M) * LOG2E) : 0.f;
        L += pact[k2];
    }

    float acc = 0.f;
#pragma unroll
    for (int c = 0; c < NCHUNK; c++) acc += wc_s[c] * g_o[pair][c][qi][tid];
#pragma unroll
    for (int k2 = 0; k2 < 4; k2++) acc += pact[k2] * g_vact[b][kvh][k2][tid];

    g_attn[b * 4 + ql][h * HDIM + tid] = acc / L;
}

// ---------------- kernel 5: O projection, REDG directly into d_out ----------------
__global__ void __launch_bounds__(128) k_oproj(const float* __restrict__ wo,
                                               float* __restrict__ out)
{
    __shared__ float2 hs[16][128];
    const int tile = blockIdx.x;    // 0..7
    const int ks   = blockIdx.y;    // 0..31
    const int tid  = threadIdx.x;

    for (int i = tid; i < 16 * 128; i += 128) {
        int r = i >> 7, c = i & 127;
        float v = g_attn[r][ks * 128 + c];
        hs[r][c] = make_float2(v, v);
    }
    __syncthreads();

    const int col = tile * 512 + tid * 4;
    const float* wp = wo + (size_t)(ks * 128) * 4096 + col;

    ull accA[16], accB[16];
#pragma unroll
    for (int r = 0; r < 16; r++) { accA[r] = 0ull; accB[r] = 0ull; }

#pragma unroll 8
    for (int kk = 0; kk < 128; kk++) {
        F4U w; w.f = *reinterpret_cast<const float4*>(wp);
        wp += 4096;
#pragma unroll
        for (int r = 0; r < 16; r++) {
            ull h2 = *reinterpret_cast<const ull*>(&hs[r][kk]);
            fma2(accA[r], h2, w.u[0]);
            fma2(accB[r], h2, w.u[1]);
        }
    }
#pragma unroll
    for (int r = 0; r < 16; r++) {
        float* op = &out[r * 4096 + col];
        atomicAdd(op + 0, lo32(accA[r]));   // result unused -> REDG
        atomicAdd(op + 1, hi32(accA[r]));
        atomicAdd(op + 2, lo32(accB[r]));
        atomicAdd(op + 3, hi32(accB[r]));
    }
}

// ---------------- launch ----------------
extern "C" void kernel_launch(void* const* d_in, const int* in_sizes, int n_in,
                              void* d_out, int out_size)
{
    const float* h  = (const float*)d_in[0];
    const float* pk = (const float*)d_in[1];
    const float* pv = (const float*)d_in[2];
    const float* wq = (const float*)d_in[3];
    const float* wk = (const float*)d_in[4];
    const float* wv = (const float*)d_in[5];
    const float* wo = (const float*)d_in[6];
    float* out = (float*)d_out;

    cudaFuncSetAttribute(k_attn, cudaFuncAttributeMaxDynamicSharedMemorySize, SMEM_ATTN);

    k_proj   <<<dim3(12, 32), 128>>>(h, wq, wk, wv);
    k_rope   <<<dim3(48, 16), 128>>>(out);
    k_attn   <<<dim3(NCHUNK, 32), 128, SMEM_ATTN>>>(pk, pv);
    k_combine<<<dim3(16, 32), 128>>>();
    k_oproj  <<<dim3(8, 32),  128>>>(wo, out);
}

// round 9
// speedup vs baseline: 1.0900x; 1.0900x over previous
#include <cuda_runtime.h>
#include <cstdint>

#define NBB 4
#define QLEN 4
#define HIDDEN 4096
#define NHEADS 32
#define NKVH 8
#define HDIM 128
#define PRIORLEN 4096
#define BQ 16
#define NCHUNK 16          /* chunks per (b,kvh) pair */
#define CHUNK 256          /* keys per chunk */
#define QK_SCALE 0.08838834764831845f   /* 1/sqrt(128) */
#define LOG2E 1.4426950408889634f

#define KST_STRIDE 132     /* floats; 132 mod 32 = 4 -> conflict-free LDS/STS.128 */
#define P2_STRIDE  18      /* float2; stride for prob rows */
#define SC_STRIDE  36      /* float view of a p2 row */

typedef unsigned long long ull;

union F4U { float4 f; ull u[2]; };

__device__ __forceinline__ void fma2(ull &d, ull a, ull b) {
    asm("fma.rn.f32x2 %0, %1, %2, %0;" : "+l"(d) : "l"(a), "l"(b));
}
__device__ __forceinline__ float lo32(ull v) { return __uint_as_float((unsigned)(v & 0xffffffffull)); }
__device__ __forceinline__ float hi32(ull v) { return __uint_as_float((unsigned)(v >> 32)); }
__device__ __forceinline__ ull dup2(float x) {
    ull r; asm("mov.b64 %0, {%1, %1};" : "=l"(r) : "f"(x)); return r;
}

// ---------------- scratch (static device globals; no runtime alloc) ----------------
__device__ __align__(16) float g_part_qkv[32][BQ][6144];      // 12.6 MB
__device__ __align__(16) float g_q[NBB][NHEADS][QLEN][HDIM];  // scaled + rope'd
__device__ __align__(16) float g_kact[NBB][NKVH][QLEN][HDIM];
__device__ __align__(16) float g_vact[NBB][NKVH][QLEN][HDIM];
__device__ __align__(16) float g_m[32][NCHUNK][16];
__device__ __align__(16) float g_l[32][NCHUNK][16];
__device__ __align__(16) float g_o[32][NCHUNK][16][HDIM];     // 4.2 MB
__device__ __align__(16) float g_attn[BQ][4096];
__device__ __align__(16) float g_part_o[32][BQ][4096];        // 8.4 MB

// ---------------- kernel 1: QKV projection partials (k-split GEMM) ----------------
__global__ void __launch_bounds__(128) k_proj(const float* __restrict__ h,
                                              const float* __restrict__ wq,
                                              const float* __restrict__ wk,
                                              const float* __restrict__ wv)
{
    __shared__ float2 hs[16][128];
    const int tile = blockIdx.x;     // 0..11
    const int ks   = blockIdx.y;     // 0..31
    const int tid  = threadIdx.x;

    for (int i = tid; i < 16 * 128; i += 128) {
        int r = i >> 7, c = i & 127;
        float v = h[r * HIDDEN + ks * 128 + c];
        hs[r][c] = make_float2(v, v);
    }
    __syncthreads();

    const float* wbase; int wstride, colbase;
    if (tile < 8)       { wbase = wq; wstride = 4096; colbase = tile * 512; }
    else if (tile < 10) { wbase = wk; wstride = 1024; colbase = (tile - 8) * 512; }
    else                { wbase = wv; wstride = 1024; colbase = (tile - 10) * 512; }

    const float* wp = wbase + (size_t)(ks * 128) * wstride + colbase + tid * 4;

    ull accA[16], accB[16];
#pragma unroll
    for (int r = 0; r < 16; r++) { accA[r] = 0ull; accB[r] = 0ull; }

#pragma unroll 8
    for (int kk = 0; kk < 128; kk++) {
        F4U w; w.f = *reinterpret_cast<const float4*>(wp);
        wp += wstride;
#pragma unroll
        for (int r = 0; r < 16; r++) {
            ull h2 = *reinterpret_cast<const ull*>(&hs[r][kk]);
            fma2(accA[r], h2, w.u[0]);
            fma2(accB[r], h2, w.u[1]);
        }
    }

    const int gcol = tile * 512 + tid * 4;
#pragma unroll
    for (int r = 0; r < 16; r++) {
        F4U o; o.u[0] = accA[r]; o.u[1] = accB[r];
        *reinterpret_cast<float4*>(&g_part_qkv[ks][r][gcol]) = o.f;
    }
}

// ---------------- kernel 2: reduce partials + RoPE ----------------
__global__ void __launch_bounds__(128) k_rope()
{
    __shared__ float sv[128];
    const int colblk = blockIdx.x;   // 0..47
    const int row    = blockIdx.y;   // 0..15
    const int tid    = threadIdx.x;
    const int col    = colblk * 128 + tid;

    float v = 0.f;
#pragma unroll
    for (int s = 0; s < 32; s++) v += g_part_qkv[s][row][col];

    const int b = row >> 2, ql = row & 3;

    if (colblk < 40) {
        sv[tid] = v;
        __syncthreads();
        const int d = tid;
        const int j = d & 63;
        float rot = (d < 64) ? -sv[d + 64] : sv[d - 64];
        float invf = (float)exp(-(double)j * (13.815510557964274 / 64.0)); // log(1e6)/64
        float pos  = (float)(PRIORLEN + ql);
        float ang  = pos * invf;
        double ad  = (double)ang;
        float c = (float)cos(ad);
        float s = (float)sin(ad);
        float outv = v * c + rot * s;
        if (colblk < 32) {
            g_q[b][colblk][ql][d] = outv * QK_SCALE;
        } else {
            g_kact[b][colblk - 32][ql][d] = outv;
        }
    } else {
        g_vact[b][colblk - 40][ql][tid] = v;
    }
}

// ---------------- kernel 3: split-KV attention partials (v4) ----------------
// grid (NCHUNK, 32 pairs), 256 threads = 8 warps. Chunk = 256 keys; warp owns 32
// keys, staged warp-privately in two 16-key tiles (coalesced LDG, __syncwarp only).
// Score dots: lane<16 = dims 0..63, lane>=16 = dims 64..127 of key (lane&15);
// halves combined with 16 shuffles per tile. Raw scores -> smem; block-wide
// max/exp; PV with lane=dim broadcast-FMA2.
// smem: kst 8*16*132*4 = 67,584 | q2s 8,192 | p2 36,864 | wm/wl 1,024 = 113,664
#define SMEM_ATTN 113664

__global__ void __launch_bounds__(256, 2) k_attn(const float* __restrict__ pk,
                                                 const float* __restrict__ pv)
{
    extern __shared__ char smraw[];
    float*  kst = reinterpret_cast<float*>(smraw);                   // [8][16][132]
    float2* q2s = reinterpret_cast<float2*>(smraw + 67584);          // [d][qp]
    float2* p2  = reinterpret_cast<float2*>(smraw + 67584 + 8192);   // [key][qi] dup
    float*  sc  = reinterpret_cast<float*>(p2);                      // raw-score view
    float*  wm  = reinterpret_cast<float*>(smraw + 67584 + 8192 + 36864); // [8][16]
    float*  wl  = wm + 128;                                               // [8][16]

    const int pair = blockIdx.y;       // 0..31
    const int cblk = blockIdx.x;       // 0..NCHUNK-1
    const int b = pair >> 3, kvh = pair & 7;
    const int tid = threadIdx.x;
    const int w = tid >> 5, lane = tid & 31;
    const int hh = lane >> 4;          // dim half
    const int kj = lane & 15;          // key-within-tile
    const int key0 = cblk * CHUNK;

    // stage q into smem as f32x2 qi-pairs: q2s[d*8+qp] = (q[2qp][d], q[2qp+1][d])
    for (int i = tid; i < 128 * 8; i += 256) {
        int d = i >> 3, qp = i & 7;
        int qi0 = 2 * qp, qi1 = 2 * qp + 1;
        q2s[i] = make_float2(g_q[b][kvh * 4 + (qi0 >> 2)][qi0 & 3][d],
                             g_q[b][kvh * 4 + (qi1 >> 2)][qi1 & 3][d]);
    }
    __syncthreads();

    const float* kchunk = pk + ((size_t)(b * NKVH + kvh) * PRIORLEN + key0) * HDIM;

    // ---- score phase: 2 warp-private 16-key tiles ----
#pragma unroll
    for (int t = 0; t < 2; t++) {
        const float* kb = kchunk + (size_t)(w * 32 + t * 16) * HDIM + lane * 4;
        // stage 16 keys coalesced, register-batched by 8 for MLP
        {
            float4 tmp[8];
#pragma unroll
            for (int j = 0; j < 8; j++) tmp[j] = *reinterpret_cast<const float4*>(kb + (size_t)j * HDIM);
#pragma unroll
            for (int j = 0; j < 8; j++) *reinterpret_cast<float4*>(&kst[(w * 16 + j) * KST_STRIDE + lane * 4]) = tmp[j];
#pragma unroll
            for (int j = 0; j < 8; j++) tmp[j] = *reinterpret_cast<const float4*>(kb + (size_t)(j + 8) * HDIM);
#pragma unroll
            for (int j = 0; j < 8; j++) *reinterpret_cast<float4*>(&kst[(w * 16 + j + 8) * KST_STRIDE + lane * 4]) = tmp[j];
        }
        __syncwarp();

        // compute: thread covers 64 dims (half hh) of key kj, all 16 qi
        ull acc[8];
#pragma unroll
        for (int qp = 0; qp < 8; qp++) acc[qp] = 0ull;
        const int krow = (w * 16 + kj) * KST_STRIDE + hh * 64;
#pragma unroll 4
        for (int d4 = 0; d4 < 16; d4++) {
            float4 kv = *reinterpret_cast<const float4*>(&kst[krow + d4 * 4]);
            float ka[4] = {kv.x, kv.y, kv.z, kv.w};
#pragma unroll
            for (int dd = 0; dd < 4; dd++) {
                ull kd = dup2(ka[dd]);
                const float4* qrow = reinterpret_cast<const float4*>(&q2s[(hh * 64 + d4 * 4 + dd) * 8]);
#pragma unroll
                for (int q4 = 0; q4 < 4; q4++) {
                    F4U qq; qq.f = qrow[q4];   // broadcast LDS.128
                    fma2(acc[2 * q4],     kd, qq.u[0]);
                    fma2(acc[2 * q4 + 1], kd, qq.u[1]);
                }
            }
        }

        // combine dim halves: thread pair (lane, lane^16)
        float s[16];
#pragma unroll
        for (int qp = 0; qp < 8; qp++) {
            float a0 = lo32(acc[qp]), a1 = hi32(acc[qp]);
            a0 += __shfl_xor_sync(0xffffffffu, a0, 16);
            a1 += __shfl_xor_sync(0xffffffffu, a1, 16);
            s[2 * qp] = a0; s[2 * qp + 1] = a1;
        }
        // write this half's 8 qi values as raw scores
        const int key = w * 32 + t * 16 + kj;
        float* dst = &sc[key * SC_STRIDE + hh * 8];
        if (hh == 0) {
            *reinterpret_cast<float4*>(dst)     = make_float4(s[0], s[1], s[2], s[3]);
            *reinterpret_cast<float4*>(dst + 4) = make_float4(s[4], s[5], s[6], s[7]);
        } else {
            *reinterpret_cast<float4*>(dst)     = make_float4(s[8], s[9], s[10], s[11]);
            *reinterpret_cast<float4*>(dst + 4) = make_float4(s[12], s[13], s[14], s[15]);
        }
        __syncwarp();   // kst reads done before next tile's STS
    }
    __syncthreads();    // all raw scores visible

    // ---- max / exp / l : thread owns key = tid ----
    float s[16];
    {
        const float* src = &sc[tid * SC_STRIDE];
#pragma unroll
        for (int c4 = 0; c4 < 4; c4++) {
            float4 v4 = *reinterpret_cast<const float4*>(src + c4 * 4);
            s[4 * c4] = v4.x; s[4 * c4 + 1] = v4.y; s[4 * c4 + 2] = v4.z; s[4 * c4 + 3] = v4.w;
        }
    }
    float m16[16];
#pragma unroll
    for (int qi = 0; qi < 16; qi++) m16[qi] = s[qi];
#pragma unroll
    for (int off = 16; off >= 1; off >>= 1) {
#pragma unroll
        for (int qi = 0; qi < 16; qi++)
            m16[qi] = fmaxf(m16[qi], __shfl_xor_sync(0xffffffffu, m16[qi], off));
    }
    if (lane == 0) {
#pragma unroll
        for (int qi = 0; qi < 16; qi++) wm[w * 16 + qi] = m16[qi];
    }
    __syncthreads();

    float p[16], l16[16];
#pragma unroll
    for (int qi = 0; qi < 16; qi++) {
        float mq = wm[qi];
#pragma unroll
        for (int ww = 1; ww < 8; ww++) mq = fmaxf(mq, wm[ww * 16 + qi]);   // broadcast LDS
        p[qi] = exp2f((s[qi] - mq) * LOG2E);
        l16[qi] = p[qi];
    }
    // duplicated probs, key-major
#pragma unroll
    for (int qp = 0; qp < 8; qp++) {
        *reinterpret_cast<float4*>(&p2[tid * P2_STRIDE + 2 * qp]) =
            make_float4(p[2 * qp], p[2 * qp], p[2 * qp + 1], p[2 * qp + 1]);
    }
#pragma unroll
    for (int off = 16; off >= 1; off >>= 1) {
#pragma unroll
        for (int qi = 0; qi < 16; qi++)
            l16[qi] += __shfl_xor_sync(0xffffffffu, l16[qi], off);
    }
    if (lane == 0) {
#pragma unroll
        for (int qi = 0; qi < 16; qi++) wl[w * 16 + qi] = l16[qi];
    }
    __syncthreads();    // p2 + wl complete
    if (tid < 16) {
        float mq = wm[tid], lq = wl[tid];
#pragma unroll
        for (int ww = 1; ww < 8; ww++) { mq = fmaxf(mq, wm[ww * 16 + tid]); lq += wl[ww * 16 + tid]; }
        g_m[pair][cblk][tid] = mq;
        g_l[pair][cblk][tid] = lq;
    }

    // ---- PV phase: warp w handles keys [w*32, w*32+32), lane = dim-group ----
    ull oA[16], oB[16];
#pragma unroll
    for (int qi = 0; qi < 16; qi++) { oA[qi] = 0ull; oB[qi] = 0ull; }
    const float* vb = pv + ((size_t)(b * NKVH + kvh) * PRIORLEN + key0 + w * 32) * HDIM + lane * 4;
#pragma unroll 4
    for (int i = 0; i < 32; i++) {
        F4U vt; vt.f = *reinterpret_cast<const float4*>(vb + (size_t)i * HDIM);
        const float4* prow = reinterpret_cast<const float4*>(&p2[(w * 32 + i) * P2_STRIDE]);
#pragma unroll
        for (int q4 = 0; q4 < 8; q4++) {
            F4U pp; pp.f = prow[q4];   // broadcast LDS.128
            fma2(oA[2 * q4],     pp.u[0], vt.u[0]);
            fma2(oB[2 * q4],     pp.u[0], vt.u[1]);
            fma2(oA[2 * q4 + 1], pp.u[1], vt.u[0]);
            fma2(oB[2 * q4 + 1], pp.u[1], vt.u[1]);
        }
    }
    __syncthreads();   // kst reads long done; safe to overlay

    // reduce 8 warp partials through smem (overlay on kst: 64KB needed, 66KB avail)
    float* osum = kst;
#pragma unroll
    for (int qi = 0; qi < 16; qi++) {
        F4U o; o.u[0] = oA[qi]; o.u[1] = oB[qi];
        *reinterpret_cast<float4*>(&osum[(w * 16 + qi) * 128 + lane * 4]) = o.f;
    }
    __syncthreads();
    float* go = &g_o[pair][cblk][0][0];
#pragma unroll
    for (int i = 0; i < 8; i++) {
        int idx = i * 256 + tid;          // qi*128 + d
        float v = 0.f;
#pragma unroll
        for (int ww = 0; ww < 8; ww++) v += osum[ww * 2048 + idx];
        go[idx] = v;
    }
}

// ---------------- kernel 4: combine chunks + causal active keys ----------------
__global__ void __launch_bounds__(128) k_combine()
{
    __shared__ float wc_s[NCHUNK], wl_s[NCHUNK], sact[4];
    const int qi = blockIdx.x, pair = blockIdx.y;
    const int b = pair >> 3, kvh = pair & 7, hl = qi >> 2, ql = qi & 3;
    const int h = kvh * 4 + hl;
    const int tid = threadIdx.x, w = tid >> 5, lane = tid & 31;

    {
        float4 qv = *reinterpret_cast<const float4*>(&g_q[b][h][ql][lane * 4]);
        float4 kv = *reinterpret_cast<const float4*>(&g_kact[b][kvh][w][lane * 4]);
        float d = qv.x * kv.x + qv.y * kv.y + qv.z * kv.z + qv.w * kv.w;
#pragma unroll
        for (int off = 16; off >= 1; off >>= 1) d += __shfl_xor_sync(0xffffffffu, d, off);
        if (lane == 0) sact[w] = d;
    }
    if (tid < NCHUNK) wc_s[tid] = g_m[pair][tid][qi];
    __syncthreads();

    float M = -3.0e38f;
#pragma unroll
    for (int c = 0; c < NCHUNK; c++) M = fmaxf(M, wc_s[c]);
#pragma unroll
    for (int k2 = 0; k2 < 4; k2++) if (k2 <= ql) M = fmaxf(M, sact[k2]);
    __syncthreads();

    if (tid < NCHUNK) {
        float e = exp2f((wc_s[tid] - M) * LOG2E);
        wl_s[tid] = e * g_l[pair][tid][qi];
        wc_s[tid] = e;
    }
    __syncthreads();

    float L = 0.f;
#pragma unroll
    for (int c = 0; c < NCHUNK; c++) L += wl_s[c];
    float pact[4];
#pragma unroll
    for (int k2 = 0; k2 < 4; k2++) {
        pact[k2] = (k2 <= ql) ? exp2f((sact[k2] - M) * LOG2E) : 0.f;
        L += pact[k2];
    }

    float acc = 0.f;
#pragma unroll
    for (int c = 0; c < NCHUNK; c++) acc += wc_s[c] * g_o[pair][c][qi][tid];
#pragma unroll
    for (int k2 = 0; k2 < 4; k2++) acc += pact[k2] * g_vact[b][kvh][k2][tid];

    g_attn[b * 4 + ql][h * HDIM + tid] = acc / L;
}

// ---------------- kernel 5: O projection partials ----------------
__global__ void __launch_bounds__(128) k_oproj(const float* __restrict__ wo)
{
    __shared__ float2 hs[16][128];
    const int tile = blockIdx.x;    // 0..7
    const int ks   = blockIdx.y;    // 0..31
    const int tid  = threadIdx.x;

    for (int i = tid; i < 16 * 128; i += 128) {
        int r = i >> 7, c = i & 127;
        float v = g_attn[r][ks * 128 + c];
        hs[r][c] = make_float2(v, v);
    }
    __syncthreads();

    const int col = tile * 512 + tid * 4;
    const float* wp = wo + (size_t)(ks * 128) * 4096 + col;

    ull accA[16], accB[16];
#pragma unroll
    for (int r = 0; r < 16; r++) { accA[r] = 0ull; accB[r] = 0ull; }

#pragma unroll 8
    for (int kk = 0; kk < 128; kk++) {
        F4U w; w.f = *reinterpret_cast<const float4*>(wp);
        wp += 4096;
#pragma unroll
        for (int r = 0; r < 16; r++) {
            ull h2 = *reinterpret_cast<const ull*>(&hs[r][kk]);
            fma2(accA[r], h2, w.u[0]);
            fma2(accB[r], h2, w.u[1]);
        }
    }
#pragma unroll
    for (int r = 0; r < 16; r++) {
        F4U o; o.u[0] = accA[r]; o.u[1] = accB[r];
        *reinterpret_cast<float4*>(&g_part_o[ks][r][col]) = o.f;
    }
}

// ---------------- kernel 6: final reduce into d_out ----------------
__global__ void __launch_bounds__(256) k_oreduce(float* __restrict__ out)
{
    const int idx = blockIdx.x * 256 + threadIdx.x;   // 0..65535
    const float* base = &g_part_o[0][0][0];
    float v = 0.f;
#pragma unroll
    for (int s = 0; s < 32; s++) v += base[(size_t)s * (BQ * 4096) + idx];
    out[idx] = v;
}

// ---------------- launch ----------------
extern "C" void kernel_launch(void* const* d_in, const int* in_sizes, int n_in,
                              void* d_out, int out_size)
{
    const float* h  = (const float*)d_in[0];
    const float* pk = (const float*)d_in[1];
    const float* pv = (const float*)d_in[2];
    const float* wq = (const float*)d_in[3];
    const float* wk = (const float*)d_in[4];
    const float* wv = (const float*)d_in[5];
    const float* wo = (const float*)d_in[6];
    float* out = (float*)d_out;

    cudaFuncSetAttribute(k_attn, cudaFuncAttributeMaxDynamicSharedMemorySize, SMEM_ATTN);

    k_proj   <<<dim3(12, 32), 128>>>(h, wq, wk, wv);
    k_rope   <<<dim3(48, 16), 128>>>();
    k_attn   <<<dim3(NCHUNK, 32), 256, SMEM_ATTN>>>(pk, pv);
    k_combine<<<dim3(16, 32), 128>>>();
    k_oproj  <<<dim3(8, 32),  128>>>(wo);
    k_oreduce<<<256, 256>>>(out);
}